// round 1
// baseline (speedup 1.0000x reference)
#include <cuda_runtime.h>

#define BDIM 16
#define FIN  3
#define NV   170
#define TT   288
#define HCH  64
#define OCH  64
#define BT   (BDIM*TT)          // 4608 (b,t) pairs

#define TPITCH 172              // t_sT row pitch (even, 8B-align for v2 loads)
#define CPITCH 172              // cheb_sT row pitch

// smem carve (floats)
#define S_TST   0                         // 64*172      = 11008
#define S_US    (S_TST + 64*TPITCH)       // 170*64      = 10880
#define S_THETA (S_US + NV*64)            // 64*64       = 4096
#define S_CHEB  (S_THETA + 64*64)         // 8*172       = 1376
#define S_CWB   (S_CHEB + 8*CPITCH)       // 576+64      = 640
#define SMEM_FLOATS (S_CWB + 640)         // 28000
#define SMEM_BYTES  (SMEM_FLOATS * 4)     // 112000

// scratch for [bt][n][o] pre-transpose output (~200.5 MB)
__device__ float g_tmp[(size_t)BT * NV * OCH];

// ---- packed f32x2 helpers (sm_100a FP32x2 pipe; ptxas never emits these) ----
__device__ __forceinline__ unsigned long long pk2(float x, float y) {
    unsigned long long r;
    asm("mov.b64 %0, {%1, %2};" : "=l"(r) : "f"(x), "f"(y));
    return r;
}
__device__ __forceinline__ void upk2(unsigned long long v, float& x, float& y) {
    asm("mov.b64 {%0, %1}, %2;" : "=f"(x), "=f"(y) : "l"(v));
}
__device__ __forceinline__ void fma2(unsigned long long& d, unsigned long long a,
                                     unsigned long long b) {
    asm("fma.rn.f32x2 %0, %1, %2, %0;" : "+l"(d) : "l"(a), "l"(b));
}

// Fused: temporal conv -> (k=0 identity) theta -> cheb(k=1,2) -> relu -> +res.
// One CTA per (b,t). 256 thr = 16 o-lanes x 16 row-groups.
// Thread owns row-pairs n = 2*ng + 32*p (p=0..5; p=5 valid iff ng<5) and
// cols o = 4*olane .. 4*olane+3. Accumulators packed over the row pair.
__global__ void __launch_bounds__(256, 2)
fused_kernel(const float* __restrict__ x,
             const float* __restrict__ cheb,
             const float* __restrict__ cw,
             const float* __restrict__ cb,
             const float* __restrict__ theta,
             const float* __restrict__ rw,
             const float* __restrict__ rb)
{
    extern __shared__ float smem[];
    float* t_sT    = smem + S_TST;    // [c][m] transposed conv output
    float* u_s     = smem + S_US;     // [m][o]
    float* theta_s = smem + S_THETA;  // [c][o] one k at a time
    float* cheb_sT = smem + S_CHEB;   // [mj][n] chunk, transposed
    float* cwb     = smem + S_CWB;    // conv w (576) + conv b (64)
    float* xs      = u_s;             // alias: x slice used only in conv phase

    const int tid = threadIdx.x;
    const int bt  = blockIdx.x;
    const int b   = bt / TT;
    const int t   = bt - b * TT;

    // ---- Phase A0: stage x[b, :, :, t-1..t+1] (zero-padded) + conv weights ----
    for (int i = tid; i < FIN * NV * 3; i += 256) {
        int f = i / (NV * 3);
        int r = i - f * NV * 3;
        int m = r / 3;
        int dt = r - m * 3;
        int tt = t + dt - 1;
        float v = 0.f;
        if (tt >= 0 && tt < TT) v = x[((b * FIN + f) * NV + m) * TT + tt];
        xs[i] = v;
    }
    for (int i = tid; i < 576; i += 256) cwb[i] = cw[i];
    if (tid < 64) cwb[576 + tid] = cb[tid];
    __syncthreads();

    // ---- Phase A: temporal conv + ReLU -> t_sT[c][m] ----
    {
        const int c = tid & 63;
        float w[9];
#pragma unroll
        for (int q = 0; q < 9; q++) w[q] = cwb[c * 9 + q];
        const float bias = cwb[576 + c];
        for (int m = tid >> 6; m < NV; m += 4) {
            float a = bias;
#pragma unroll
            for (int f = 0; f < FIN; f++)
#pragma unroll
                for (int dt = 0; dt < 3; dt++)
                    a += xs[(f * NV + m) * 3 + dt] * w[f * 3 + dt];
            t_sT[c * TPITCH + m] = fmaxf(a, 0.f);
        }
    }
    __syncthreads();

    const int olane = tid & 15;
    const int ng    = tid >> 4;
    const bool p5ok = (ng < 5);   // pair p=5 (rows 160+2ng) valid iff 2ng+160 < 170

    unsigned long long acc[6][4];
#pragma unroll
    for (int p = 0; p < 6; p++)
#pragma unroll
        for (int j = 0; j < 4; j++) acc[p][j] = 0ull;

    // ---- k = 0: cheb[0] == I  =>  acc = t @ theta0 directly ----
    for (int i = tid; i < 4096; i += 256) theta_s[i] = theta[i];
    __syncthreads();
    for (int c = 0; c < 64; c++) {
        const float4 th4 = *(const float4*)&theta_s[c * 64 + 4 * olane];
        unsigned long long tv0 = pk2(th4.x, th4.x);
        unsigned long long tv1 = pk2(th4.y, th4.y);
        unsigned long long tv2p = pk2(th4.z, th4.z);
        unsigned long long tv3 = pk2(th4.w, th4.w);
#pragma unroll
        for (int p = 0; p < 6; p++) {
            if (p < 5 || p5ok) {
                unsigned long long tpair =
                    *(const unsigned long long*)&t_sT[c * TPITCH + 2 * ng + 32 * p];
                fma2(acc[p][0], tpair, tv0);
                fma2(acc[p][1], tpair, tv1);
                fma2(acc[p][2], tpair, tv2p);
                fma2(acc[p][3], tpair, tv3);
            }
        }
    }

    // ---- k = 1, 2: u = t @ theta_k (to smem), then acc += cheb_k @ u ----
#pragma unroll 1
    for (int k = 1; k < 3; k++) {
        __syncthreads();                          // previous theta_s / u_s use done
        for (int i = tid; i < 4096; i += 256) theta_s[i] = theta[k * 4096 + i];
        __syncthreads();

        // u-compute in two halves (limits live registers)
#pragma unroll 1
        for (int h = 0; h < 2; h++) {
            unsigned long long u2[3][4];
#pragma unroll
            for (int pp = 0; pp < 3; pp++)
#pragma unroll
                for (int j = 0; j < 4; j++) u2[pp][j] = 0ull;

            for (int c = 0; c < 64; c++) {
                const float4 th4 = *(const float4*)&theta_s[c * 64 + 4 * olane];
                unsigned long long tv0 = pk2(th4.x, th4.x);
                unsigned long long tv1 = pk2(th4.y, th4.y);
                unsigned long long tv2p = pk2(th4.z, th4.z);
                unsigned long long tv3 = pk2(th4.w, th4.w);
#pragma unroll
                for (int pp = 0; pp < 3; pp++) {
                    const int p = h * 3 + pp;
                    if (p < 5 || p5ok) {
                        unsigned long long tpair =
                            *(const unsigned long long*)&t_sT[c * TPITCH + 2 * ng + 32 * p];
                        fma2(u2[pp][0], tpair, tv0);
                        fma2(u2[pp][1], tpair, tv1);
                        fma2(u2[pp][2], tpair, tv2p);
                        fma2(u2[pp][3], tpair, tv3);
                    }
                }
            }
#pragma unroll
            for (int pp = 0; pp < 3; pp++) {
                const int p = h * 3 + pp;
                if (p < 5 || p5ok) {
                    const int n = 2 * ng + 32 * p;
                    float lo[4], hi[4];
#pragma unroll
                    for (int j = 0; j < 4; j++) upk2(u2[pp][j], lo[j], hi[j]);
                    *(float4*)&u_s[n * 64 + 4 * olane] =
                        make_float4(lo[0], lo[1], lo[2], lo[3]);
                    *(float4*)&u_s[(n + 1) * 64 + 4 * olane] =
                        make_float4(hi[0], hi[1], hi[2], hi[3]);
                }
            }
        }
        __syncthreads();

        // cheb phase: chunks of 8 m-columns staged (transposed) in smem
        for (int mc = 0; mc < NV; mc += 8) {
            for (int i = tid; i < NV * 8; i += 256) {
                int n = i >> 3;
                int mj = i & 7;
                float v = 0.f;
                if (mc + mj < NV) v = cheb[(k * NV + n) * NV + mc + mj];
                cheb_sT[mj * CPITCH + n] = v;
            }
            __syncthreads();
#pragma unroll
            for (int mj = 0; mj < 8; mj++) {
                const int m = mc + mj;  // m>=170: cheb entries are 0, u read is
                                        // in-bounds smem garbage * 0 -> no-op
                const float4 uv4 = *(const float4*)&u_s[m * 64 + 4 * olane];
                unsigned long long uv0 = pk2(uv4.x, uv4.x);
                unsigned long long uv1 = pk2(uv4.y, uv4.y);
                unsigned long long uv2 = pk2(uv4.z, uv4.z);
                unsigned long long uv3 = pk2(uv4.w, uv4.w);
#pragma unroll
                for (int p = 0; p < 6; p++) {
                    if (p < 5 || p5ok) {
                        unsigned long long cv2 =
                            *(const unsigned long long*)&cheb_sT[mj * CPITCH + 2 * ng + 32 * p];
                        fma2(acc[p][0], cv2, uv0);
                        fma2(acc[p][1], cv2, uv1);
                        fma2(acc[p][2], cv2, uv2);
                        fma2(acc[p][3], cv2, uv3);
                    }
                }
            }
            __syncthreads();
        }
    }

    // ---- finale: relu(acc) + residual, store [bt][n][o] coalesced ----
    float rwv[12], rbv[4];
#pragma unroll
    for (int j = 0; j < 4; j++) {
        rbv[j] = rb[4 * olane + j];
#pragma unroll
        for (int f = 0; f < FIN; f++) rwv[j * 3 + f] = rw[(4 * olane + j) * 3 + f];
    }
#pragma unroll
    for (int p = 0; p < 6; p++) {
        if (p < 5 || p5ok) {
            const int n = 2 * ng + 32 * p;
            float lo[4], hi[4];
#pragma unroll
            for (int j = 0; j < 4; j++) upk2(acc[p][j], lo[j], hi[j]);
            float xa[3], xb[3];
#pragma unroll
            for (int f = 0; f < FIN; f++) {
                xa[f] = x[((b * FIN + f) * NV + n) * TT + t];
                xb[f] = x[((b * FIN + f) * NV + n + 1) * TT + t];
            }
            float4 o0, o1;
#pragma unroll
            for (int j = 0; j < 4; j++) {
                float r0 = rbv[j] + xa[0] * rwv[j * 3] + xa[1] * rwv[j * 3 + 1] + xa[2] * rwv[j * 3 + 2];
                float r1 = rbv[j] + xb[0] * rwv[j * 3] + xb[1] * rwv[j * 3 + 1] + xb[2] * rwv[j * 3 + 2];
                ((float*)&o0)[j] = fmaxf(lo[j], 0.f) + r0;
                ((float*)&o1)[j] = fmaxf(hi[j], 0.f) + r1;
            }
            *(float4*)&g_tmp[((size_t)bt * NV + n) * OCH + 4 * olane] = o0;
            *(float4*)&g_tmp[((size_t)bt * NV + n + 1) * OCH + 4 * olane] = o1;
        }
    }
}

// [b][t][n][o] -> [b][o][n][t] tiled transpose over (t,o) for each (b,n)
__global__ void transpose_kernel(float* __restrict__ out)
{
    __shared__ float tile[32][33];
    const int bz = blockIdx.z;
    const int b = bz / NV;
    const int n = bz - b * NV;
    const int t0 = blockIdx.x * 32;
    const int o0 = blockIdx.y * 32;
    const int tx = threadIdx.x, ty = threadIdx.y;
#pragma unroll
    for (int yy = ty; yy < 32; yy += 8)
        tile[yy][tx] = g_tmp[(((size_t)b * TT + t0 + yy) * NV + n) * OCH + o0 + tx];
    __syncthreads();
#pragma unroll
    for (int yy = ty; yy < 32; yy += 8)
        out[(((size_t)b * OCH + o0 + yy) * NV + n) * TT + t0 + tx] = tile[tx][yy];
}

extern "C" void kernel_launch(void* const* d_in, const int* in_sizes, int n_in,
                              void* d_out, int out_size)
{
    const float* x     = (const float*)d_in[0];
    // d_in[1] = adj (unused by forward)
    const float* cheb  = (const float*)d_in[2];
    const float* cw    = (const float*)d_in[3];
    const float* cb    = (const float*)d_in[4];
    const float* theta = (const float*)d_in[5];
    const float* rw    = (const float*)d_in[6];
    const float* rb    = (const float*)d_in[7];

    cudaFuncSetAttribute(fused_kernel,
                         cudaFuncAttributeMaxDynamicSharedMemorySize, SMEM_BYTES);

    fused_kernel<<<BT, 256, SMEM_BYTES>>>(x, cheb, cw, cb, theta, rw, rb);

    dim3 tg(TT / 32, OCH / 32, BDIM * NV);
    transpose_kernel<<<tg, dim3(32, 8)>>>((float*)d_out);
}

// round 3
// speedup vs baseline: 1.0577x; 1.0577x over previous
#include <cuda_runtime.h>

#define BDIM 16
#define FIN  3
#define NV   170
#define TT   288
#define OCH  64
#define BT   (BDIM*TT)          // 4608 (b,t) pairs

#define TPITCH 192              // t_sT row pitch
#define MPAD   192              // padded vertex dim for chebT

// smem carve (floats)
#define S_TST   0                         // 64*192  = 12288
#define S_US    (S_TST + 64*TPITCH)       // 192*64  = 12288
#define S_THETA (S_US + MPAD*64)          // 64*64   = 4096
#define S_CHEB  (S_THETA + 4096)          // 2*32*192= 12288 (double buffer)
#define S_CWB   (S_CHEB + 2*32*MPAD)      // 576+64  = 640
#define SMEM_FLOATS (S_CWB + 640)         // 41600
#define SMEM_BYTES  (SMEM_FLOATS * 4)     // 166400

// scratch: [bt][n][o] pre-transpose output (~200.5 MB) + transposed cheb
__device__ float g_tmp[(size_t)BT * NV * OCH];
__device__ float g_chebT[2 * MPAD * MPAD];   // [k-1][m][n], zero-padded

// ---- packed f32x2 helpers ----
__device__ __forceinline__ unsigned long long pk2(float x, float y) {
    unsigned long long r;
    asm("mov.b64 %0, {%1, %2};" : "=l"(r) : "f"(x), "f"(y));
    return r;
}
__device__ __forceinline__ void upk2(unsigned long long v, float& x, float& y) {
    asm("mov.b64 {%0, %1}, %2;" : "=f"(x), "=f"(y) : "l"(v));
}
__device__ __forceinline__ void fma2(unsigned long long& d, unsigned long long a,
                                     unsigned long long b) {
    asm("fma.rn.f32x2 %0, %1, %2, %0;" : "+l"(d) : "l"(a), "l"(b));
}

// ---- cp.async helpers ----
__device__ __forceinline__ void cp16(float* s, const float* g) {
    unsigned sa = (unsigned)__cvta_generic_to_shared(s);
    asm volatile("cp.async.cg.shared.global [%0], [%1], 16;" :: "r"(sa), "l"(g));
}
#define CP_COMMIT() asm volatile("cp.async.commit_group;")
#define CP_WAIT(N)  asm volatile("cp.async.wait_group %0;" :: "n"(N))

// prep: g_chebT[k-1][m][n] = cheb[k][n][m], zero-padded to 192x192
__global__ void prep_chebT(const float* __restrict__ cheb)
{
    int i = blockIdx.x * 256 + threadIdx.x;    // < 2*192*192
    int k = i / (MPAD * MPAD);
    int r = i - k * MPAD * MPAD;
    int m = r / MPAD;
    int n = r - m * MPAD;
    float v = 0.f;
    if (m < NV && n < NV) v = cheb[(k + 1) * NV * NV + n * NV + m];
    g_chebT[i] = v;
}

// Fused: conv -> (k=0 identity) theta -> cheb(k=1,2) -> relu -> +res.
// One CTA (512 thr) per (b,t). 16 o-lanes x 32 row-groups.
// Thread owns row-pairs n = 2*ng + 64*p (p=0..2; p=2 valid iff ng<21),
// cols o = 4*olane..+3. Accumulators packed over the row pair.
__global__ void __launch_bounds__(512, 1)
fused_kernel(const float* __restrict__ x,
             const float* __restrict__ cw,
             const float* __restrict__ cb,
             const float* __restrict__ theta,
             const float* __restrict__ rw,
             const float* __restrict__ rb)
{
    extern __shared__ float smem[];
    float* t_sT    = smem + S_TST;    // [c][m] conv output, transposed
    float* u_s     = smem + S_US;     // [m][o]
    float* theta_s = smem + S_THETA;  // [c][o] one k at a time
    float* chebBuf = smem + S_CHEB;   // 2 x [32][192] chunks of chebT
    float* cwb     = smem + S_CWB;    // conv w (576) + conv b (64)
    float* xs      = u_s;             // alias: x slice, dead after conv phase

    const int tid = threadIdx.x;
    const int bt  = blockIdx.x;
    const int b   = bt / TT;
    const int t   = bt - b * TT;

    // ---- stage x[b,:,:,t-1..t+1] (zero padded) + conv weights ----
    for (int i = tid; i < FIN * NV * 3; i += 512) {
        int f = i / (NV * 3);
        int r = i - f * NV * 3;
        int m = r / 3;
        int dt = r - m * 3;
        int tt = t + dt - 1;
        float v = 0.f;
        if (tt >= 0 && tt < TT) v = x[((b * FIN + f) * NV + m) * TT + tt];
        xs[i] = v;
    }
    for (int i = tid; i < 640; i += 512)                 // FIX: full 640 staged
        cwb[i] = (i < 576) ? cw[i] : cb[i - 576];
    __syncthreads();

    // ---- temporal conv + ReLU -> t_sT[c][m] ----
    {
        const int c = tid & 63;
        float w[9];
#pragma unroll
        for (int q = 0; q < 9; q++) w[q] = cwb[c * 9 + q];
        const float bias = cwb[576 + c];
        for (int m = tid >> 6; m < NV; m += 8) {
            float a = bias;
#pragma unroll
            for (int f = 0; f < FIN; f++)
#pragma unroll
                for (int dt = 0; dt < 3; dt++)
                    a += xs[(f * NV + m) * 3 + dt] * w[f * 3 + dt];
            t_sT[c * TPITCH + m] = fmaxf(a, 0.f);
        }
    }

    const int olane = tid & 15;
    const int ng    = tid >> 4;              // 0..31
    const bool p2ok = (ng < 21);             // rows 128+2ng valid iff < 170

    unsigned long long acc[3][4];
#pragma unroll
    for (int p = 0; p < 3; p++)
#pragma unroll
        for (int j = 0; j < 4; j++) acc[p][j] = 0ull;

    // ---- k = 0: cheb[0] == I  =>  acc = t @ theta0 ----
    __syncthreads();                          // xs alias dead, t_sT ready
    for (int i = tid; i < 4096; i += 512) theta_s[i] = theta[i];
    // zero u_s pad rows (170..191): never written by u-compute, read (x0) in cheb
    for (int i = tid; i < (MPAD - NV) * 64; i += 512) u_s[NV * 64 + i] = 0.f;
    __syncthreads();
    for (int c = 0; c < 64; c++) {
        const float4 th4 = *(const float4*)&theta_s[c * 64 + 4 * olane];
        unsigned long long tv0 = pk2(th4.x, th4.x);
        unsigned long long tv1 = pk2(th4.y, th4.y);
        unsigned long long tv2 = pk2(th4.z, th4.z);
        unsigned long long tv3 = pk2(th4.w, th4.w);
#pragma unroll
        for (int p = 0; p < 3; p++) {
            if (p < 2 || p2ok) {
                unsigned long long tpair =
                    *(const unsigned long long*)&t_sT[c * TPITCH + 2 * ng + 64 * p];
                fma2(acc[p][0], tpair, tv0);
                fma2(acc[p][1], tpair, tv1);
                fma2(acc[p][2], tpair, tv2);
                fma2(acc[p][3], tpair, tv3);
            }
        }
    }

    // ---- k = 1,2: u = t @ theta_k -> smem, then acc += chebT_k^T @ u ----
#pragma unroll 1
    for (int k = 1; k < 3; k++) {
        __syncthreads();                      // theta_s / u_s / chebBuf reuse safe
        for (int i = tid; i < 4096; i += 512) theta_s[i] = theta[k * 4096 + i];

        // prefetch cheb chunks 0,1 for this k (chebBuf free here)
        const float* cbase = g_chebT + (k - 1) * MPAD * MPAD;
        {
#pragma unroll
            for (int j = 0; j < 3; j++) {
                int idx = tid + j * 512;      // 16B units within 32*192 floats
                cp16(&chebBuf[idx * 4], cbase + idx * 4);
            }
            CP_COMMIT();
#pragma unroll
            for (int j = 0; j < 3; j++) {
                int idx = tid + j * 512;
                cp16(&chebBuf[32 * MPAD + idx * 4], cbase + 32 * MPAD + idx * 4);
            }
            CP_COMMIT();
        }
        __syncthreads();                      // theta_s ready

        // u-compute (24 packed accumulators)
        unsigned long long u2[3][4];
#pragma unroll
        for (int p = 0; p < 3; p++)
#pragma unroll
            for (int j = 0; j < 4; j++) u2[p][j] = 0ull;
        for (int c = 0; c < 64; c++) {
            const float4 th4 = *(const float4*)&theta_s[c * 64 + 4 * olane];
            unsigned long long tv0 = pk2(th4.x, th4.x);
            unsigned long long tv1 = pk2(th4.y, th4.y);
            unsigned long long tv2 = pk2(th4.z, th4.z);
            unsigned long long tv3 = pk2(th4.w, th4.w);
#pragma unroll
            for (int p = 0; p < 3; p++) {
                if (p < 2 || p2ok) {
                    unsigned long long tpair =
                        *(const unsigned long long*)&t_sT[c * TPITCH + 2 * ng + 64 * p];
                    fma2(u2[p][0], tpair, tv0);
                    fma2(u2[p][1], tpair, tv1);
                    fma2(u2[p][2], tpair, tv2);
                    fma2(u2[p][3], tpair, tv3);
                }
            }
        }
#pragma unroll
        for (int p = 0; p < 3; p++) {
            if (p < 2 || p2ok) {
                const int n = 2 * ng + 64 * p;
                float lo[4], hi[4];
#pragma unroll
                for (int j = 0; j < 4; j++) upk2(u2[p][j], lo[j], hi[j]);
                *(float4*)&u_s[n * 64 + 4 * olane] =
                    make_float4(lo[0], lo[1], lo[2], lo[3]);
                *(float4*)&u_s[(n + 1) * 64 + 4 * olane] =
                    make_float4(hi[0], hi[1], hi[2], hi[3]);
            }
        }
        __syncthreads();                      // u_s ready

        // cheb phase: 6 chunks of 32 m-rows, double buffered cp.async
#pragma unroll 1
        for (int ch = 0; ch < 6; ch++) {
            if (ch < 5) { CP_WAIT(1); } else { CP_WAIT(0); }
            __syncthreads();                  // chunk ch visible to all
            const float* cbuf = &chebBuf[(ch & 1) * 32 * MPAD];
#pragma unroll 4
            for (int mj = 0; mj < 32; mj++) {
                const int m = ch * 32 + mj;   // m>=170: chebT rows zero, u_s zero
                const float4 uv4 = *(const float4*)&u_s[m * 64 + 4 * olane];
                unsigned long long uv0 = pk2(uv4.x, uv4.x);
                unsigned long long uv1 = pk2(uv4.y, uv4.y);
                unsigned long long uv2 = pk2(uv4.z, uv4.z);
                unsigned long long uv3 = pk2(uv4.w, uv4.w);
#pragma unroll
                for (int p = 0; p < 3; p++) {
                    if (p < 2 || p2ok) {
                        unsigned long long cv2 =
                            *(const unsigned long long*)&cbuf[mj * MPAD + 2 * ng + 64 * p];
                        fma2(acc[p][0], cv2, uv0);
                        fma2(acc[p][1], cv2, uv1);
                        fma2(acc[p][2], cv2, uv2);
                        fma2(acc[p][3], cv2, uv3);
                    }
                }
            }
            __syncthreads();                  // all done reading buf before refill
            if (ch + 2 < 6) {
#pragma unroll
                for (int j = 0; j < 3; j++) {
                    int idx = tid + j * 512;
                    cp16(&chebBuf[(ch & 1) * 32 * MPAD + idx * 4],
                         cbase + (ch + 2) * 32 * MPAD + idx * 4);
                }
                CP_COMMIT();
            }
        }
    }

    // ---- finale: relu(acc) + residual, store [bt][n][o] coalesced ----
    float rwv[12], rbv[4];
#pragma unroll
    for (int j = 0; j < 4; j++) {
        rbv[j] = rb[4 * olane + j];
#pragma unroll
        for (int f = 0; f < FIN; f++) rwv[j * 3 + f] = rw[(4 * olane + j) * 3 + f];
    }
#pragma unroll
    for (int p = 0; p < 3; p++) {
        if (p < 2 || p2ok) {
            const int n = 2 * ng + 64 * p;
            float lo[4], hi[4];
#pragma unroll
            for (int j = 0; j < 4; j++) upk2(acc[p][j], lo[j], hi[j]);
            float xa[3], xb[3];
#pragma unroll
            for (int f = 0; f < FIN; f++) {
                xa[f] = x[((b * FIN + f) * NV + n) * TT + t];
                xb[f] = x[((b * FIN + f) * NV + n + 1) * TT + t];
            }
            float4 o0, o1;
#pragma unroll
            for (int j = 0; j < 4; j++) {
                float r0 = rbv[j] + xa[0] * rwv[j * 3] + xa[1] * rwv[j * 3 + 1] + xa[2] * rwv[j * 3 + 2];
                float r1 = rbv[j] + xb[0] * rwv[j * 3] + xb[1] * rwv[j * 3 + 1] + xb[2] * rwv[j * 3 + 2];
                ((float*)&o0)[j] = fmaxf(lo[j], 0.f) + r0;
                ((float*)&o1)[j] = fmaxf(hi[j], 0.f) + r1;
            }
            *(float4*)&g_tmp[((size_t)bt * NV + n) * OCH + 4 * olane] = o0;
            *(float4*)&g_tmp[((size_t)bt * NV + n + 1) * OCH + 4 * olane] = o1;
        }
    }
}

// [b][t][n][o] -> [b][o][n][t]; 2 n-slices per block for MLP
__global__ void transpose_kernel(float* __restrict__ out)
{
    __shared__ float tile[2][32][33];
    const int bz = blockIdx.z;              // over BDIM * (NV/2)
    const int b = bz / (NV / 2);
    const int n0 = (bz - b * (NV / 2)) * 2;
    const int t0 = blockIdx.x * 32;
    const int o0 = blockIdx.y * 32;
    const int tx = threadIdx.x, ty = threadIdx.y;
#pragma unroll
    for (int q = 0; q < 2; q++)
#pragma unroll
        for (int yy = ty; yy < 32; yy += 8)
            tile[q][yy][tx] =
                g_tmp[(((size_t)b * TT + t0 + yy) * NV + n0 + q) * OCH + o0 + tx];
    __syncthreads();
#pragma unroll
    for (int q = 0; q < 2; q++)
#pragma unroll
        for (int yy = ty; yy < 32; yy += 8)
            out[(((size_t)b * OCH + o0 + yy) * NV + n0 + q) * TT + t0 + tx] =
                tile[q][tx][yy];
}

extern "C" void kernel_launch(void* const* d_in, const int* in_sizes, int n_in,
                              void* d_out, int out_size)
{
    const float* x     = (const float*)d_in[0];
    // d_in[1] = adj (unused by forward)
    const float* cheb  = (const float*)d_in[2];
    const float* cw    = (const float*)d_in[3];
    const float* cb    = (const float*)d_in[4];
    const float* theta = (const float*)d_in[5];
    const float* rw    = (const float*)d_in[6];
    const float* rb    = (const float*)d_in[7];

    cudaFuncSetAttribute(fused_kernel,
                         cudaFuncAttributeMaxDynamicSharedMemorySize, SMEM_BYTES);

    prep_chebT<<<(2 * MPAD * MPAD) / 256, 256>>>(cheb);
    fused_kernel<<<BT, 512, SMEM_BYTES>>>(x, cw, cb, theta, rw, rb);

    dim3 tg(TT / 32, OCH / 32, BDIM * (NV / 2));
    transpose_kernel<<<tg, dim3(32, 8)>>>((float*)d_out);
}